// round 6
// baseline (speedup 1.0000x reference)
#include <cuda_runtime.h>

#define IW 1920
#define IH 1080
#define IB 8
#define NPIX (IW * IH)
#define NTOT (IB * NPIX)
#define WPR  (IW / 32)            // 60 packed words per row
#define NWORDS (NTOT / 32)        // 518400
#define BORDER_WORDS_PER_IMG (60 + 60 + 1078 * 2)   // 2276

#define TH 24                     // output tile height (1080/24 = 45)

// Scratch (no cudaMalloc allowed)
__device__ unsigned char g_dir[NTOT];
__device__ unsigned int  g_pe0[NWORDS], g_pl0[NWORDS];   // after NMS/threshold
__device__ unsigned int  g_pe1[NWORDS], g_pl1[NWORDS];   // after hysteresis iter 1

// ---------------------------------------------------------------------------
// Kernel 1: fused gaussian(5x5) + sobel + mag*255 + ang + NMS + threshold.
// 32x24-output tile per 256-thread block; weights are immediates (FFMA-imm);
// gx/gy stored in smem at stage 2 (no per-pixel sobel recompute).
// Border words (jnp.roll wrap) recomputed by k_border afterwards.
// ---------------------------------------------------------------------------
__global__ void k_fused(const float* __restrict__ x,
                        float* __restrict__ magOut, float* __restrict__ angOut) {
    // Hardcoded problem constants (bit-identical to reference setup_inputs):
    // gaussian = [[2,4,5,4,2],[4,9,12,9,4],[5,12,15,12,5],[4,9,12,9,4],[2,4,5,4,2]]/159
    constexpr float GW[25] = {
        2.0f/159.0f, 4.0f/159.0f,  5.0f/159.0f, 4.0f/159.0f, 2.0f/159.0f,
        4.0f/159.0f, 9.0f/159.0f, 12.0f/159.0f, 9.0f/159.0f, 4.0f/159.0f,
        5.0f/159.0f,12.0f/159.0f, 15.0f/159.0f,12.0f/159.0f, 5.0f/159.0f,
        4.0f/159.0f, 9.0f/159.0f, 12.0f/159.0f, 9.0f/159.0f, 4.0f/159.0f,
        2.0f/159.0f, 4.0f/159.0f,  5.0f/159.0f, 4.0f/159.0f, 2.0f/159.0f };
    __shared__ float sin_[32][41];   // raw input, rows by-4..by+27, cols bx-4..bx+35
    __shared__ float gsm[28][37];    // smoothed/255, rows by-2..by+25, cols bx-2..bx+33
    __shared__ float magS[26][35];   // mag*255, rows by-1..by+24, cols bx-1..bx+33
    __shared__ float gxS[26][35];
    __shared__ float gyS[26][35];
    const int b  = blockIdx.z;
    const int bx = blockIdx.x * 32, by = blockIdx.y * TH;
    const int tx = threadIdx.x, ty = threadIdx.y;
    const int tid = ty * 32 + tx;
    const float* img = x + b * NPIX;
    // ---- stage 0: raw input tile (zero padded) ----
    for (int i = tid; i < 32 * 40; i += 256) {
        int r = i / 40, c = i % 40;
        int yy = by + r - 4, xx = bx + c - 4;
        float v = 0.f;
        if (yy >= 0 && yy < IH && xx >= 0 && xx < IW) v = img[yy * IW + xx];
        sin_[r][c] = v;
    }
    __syncthreads();
    // ---- stage 1: gaussian -> gsm (immediate weights, original fmaf order) ----
    for (int i = tid; i < 28 * 36; i += 256) {
        int r = i / 36, c = i % 36;
        int yy = by + r - 2, xx = bx + c - 2;
        float s = 0.f;
#pragma unroll
        for (int di = 0; di < 5; di++)
#pragma unroll
            for (int dj = 0; dj < 5; dj++)
                s = fmaf(GW[di * 5 + dj], sin_[r + di][c + dj], s);
        gsm[r][c] = (yy >= 0 && yy < IH && xx >= 0 && xx < IW) ? s * (1.0f / 255.0f) : 0.f;
    }
    __syncthreads();
    // ---- stage 2: sobel -> gx, gy, mag (zero-weight terms skipped; order kept) ----
    for (int i = tid; i < 26 * 34; i += 256) {
        int r = i / 34, c = i % 34;
        const float v00 = gsm[r+0][c+0], v01 = gsm[r+0][c+1], v02 = gsm[r+0][c+2];
        const float v10 = gsm[r+1][c+0],                      v12 = gsm[r+1][c+2];
        const float v20 = gsm[r+2][c+0], v21 = gsm[r+2][c+1], v22 = gsm[r+2][c+2];
        float gxv = 0.f;
        gxv = fmaf(-0.125f, v00, gxv);
        gxv = fmaf( 0.125f, v02, gxv);
        gxv = fmaf(-0.25f,  v10, gxv);
        gxv = fmaf( 0.25f,  v12, gxv);
        gxv = fmaf(-0.125f, v20, gxv);
        gxv = fmaf( 0.125f, v22, gxv);
        float gyv = 0.f;
        gyv = fmaf(-0.125f, v00, gyv);
        gyv = fmaf(-0.25f,  v01, gyv);
        gyv = fmaf(-0.125f, v02, gyv);
        gyv = fmaf( 0.125f, v20, gyv);
        gyv = fmaf( 0.25f,  v21, gyv);
        gyv = fmaf( 0.125f, v22, gyv);
        gxS[r][c] = gxv;
        gyS[r][c] = gyv;
        magS[r][c] = sqrtf(gxv * gxv + gyv * gyv + 1e-6f) * 255.0f;
    }
    __syncthreads();
    // ---- stage 3: per-pixel angle + outputs + NMS (3 rows per thread) ----
    const bool colBorder = (blockIdx.x == 0) | (blockIdx.x == WPR - 1);
#pragma unroll
    for (int s = 0; s < 3; s++) {
        const int o = ty + 8 * s;            // output row within tile (warp-uniform)
        const int Y = by + o;
        const int idx = b * NPIX + Y * IW + (bx + tx);
        const float gx_ = gxS[o + 1][tx + 1];
        const float gy_ = gyS[o + 1][tx + 1];
        const float m255 = magS[o + 1][tx + 1];
        magOut[idx] = m255;
        float ang = atan2f(gy_, gx_);
        float t = ang + 3.14159274101257324f;            // float32(pi)
        if (t >= 6.28318548202514648f) t -= 6.28318548202514648f;   // == fmodf(t, 2pi)
        float deg = t * 57.2957801818847656f;            // float32(180/pi)
        float am = deg;
        if (am >= 180.0f) am -= 180.0f;                  // == fmodf(deg, 180)
        if (am >= 180.0f) am -= 180.0f;
        angOut[idx] = am;
        int q = (int)rintf(deg / 45.0f);                 // round-half-even == jnp.round
        const int cls = q & 3;
        if (Y == 0 || Y == IH - 1 || colBorder)
            g_dir[idx] = (unsigned char)cls;
        // NMS from smem (interior-valid; border words overwritten by k_border)
        const int r0 = o + 1, c0 = tx + 1;
        // cls0: (y,xr)/(y,xl)  cls1: (yd,xr)/(yu,x) [ref bug kept]
        // cls2: (yd,x)/(yu,x)  cls3: (yd,xl)/(yu,xr)
        int ar = (cls == 0) ? r0 : r0 + 1;
        int ac = (cls == 2) ? c0 : ((cls == 3) ? c0 - 1 : c0 + 1);
        int cr = (cls == 0) ? r0 : r0 - 1;
        int cc = (cls == 0) ? c0 - 1 : ((cls == 3) ? c0 + 1 : c0);
        float a = magS[ar][ac];
        float c = magS[cr][cc];
        float sup = (m255 > a && m255 > c) ? m255 : 0.f;
        unsigned we = __ballot_sync(0xffffffffu, sup > 150.0f);
        unsigned wl = __ballot_sync(0xffffffffu, sup >= 50.0f && sup < 150.0f);
        if (tx == 0) {
            const int widx = (b * IH + Y) * WPR + blockIdx.x;
            g_pe0[widx] = we;
            g_pl0[widx] = wl;
        }
    }
}

// ---------------------------------------------------------------------------
// Kernel 2: recompute NMS/threshold for border words (rows 0 & 1079, word
// cols 0 & 59) with jnp.roll wrap-around. One warp per word.
// ---------------------------------------------------------------------------
__global__ void k_border(const float* __restrict__ mag) {
    const int W = blockIdx.x * 8 + threadIdx.y;          // warp id
    const int lane = threadIdx.x;
    const int b = W / BORDER_WORDS_PER_IMG;
    const int u = W % BORDER_WORDS_PER_IMG;
    int y, w;
    if (u < 60)       { y = 0;        w = u; }
    else if (u < 120) { y = IH - 1;   w = u - 60; }
    else { int v = u - 120; y = 1 + (v >> 1); w = (v & 1) ? (WPR - 1) : 0; }
    const int x = w * 32 + lane;
    const float* p = mag + b * NPIX;
    const int idx = b * NPIX + y * IW + x;
    const float m0 = p[y * IW + x];
    const int xl = (x == 0) ? (IW - 1) : (x - 1);
    const int xr = (x == IW - 1) ? 0 : (x + 1);
    const int yu = (y == 0) ? (IH - 1) : (y - 1);
    const int yd = (y == IH - 1) ? 0 : (y + 1);
    const int cls = g_dir[idx];
    int ay = (cls == 0) ? y : yd;
    int ax = (cls == 2) ? x : ((cls == 3) ? xl : xr);
    int cy = (cls == 0) ? y : yu;
    int cx = (cls == 0) ? xl : ((cls == 3) ? xr : x);
    float a = p[ay * IW + ax];
    float c = p[cy * IW + cx];
    float sup = (m0 > a && m0 > c) ? m0 : 0.f;
    unsigned we = __ballot_sync(0xffffffffu, sup > 150.0f);
    unsigned wl = __ballot_sync(0xffffffffu, sup >= 50.0f && sup < 150.0f);
    if (lane == 0) {
        const int widx = (b * IH + y) * WPR + w;
        g_pe0[widx] = we;
        g_pl0[widx] = wl;
    }
}

// ---------------------------------------------------------------------------
// Bit helper: OR of {left,center,right} horizontal neighbors of a word row.
// ---------------------------------------------------------------------------
__device__ __forceinline__ unsigned hor3(unsigned L, unsigned M, unsigned R) {
    return M | (M << 1) | (M >> 1) | (L >> 31) | (R << 31);
}

// ---------------------------------------------------------------------------
// Kernel 3: hysteresis iteration 1, fully bit-packed, word per thread.
// ---------------------------------------------------------------------------
__global__ void k_hyst1() {
    const int t = blockIdx.x * 256 + threadIdx.x;
    const int w = t % WPR;
    const int rem = t / WPR;
    const int y = rem % IH;
    const int base = t - w;
    unsigned nbr = 0, e = 0;
#pragma unroll
    for (int dy = -1; dy <= 1; dy++) {
        const int yy = y + dy;
        if (yy < 0 || yy >= IH) continue;
        const int rb = base + dy * WPR;
        unsigned L = (w > 0)       ? g_pe0[rb + w - 1] : 0u;
        unsigned M =                 g_pe0[rb + w];
        unsigned R = (w < WPR - 1) ? g_pe0[rb + w + 1] : 0u;
        nbr |= hor3(L, M, R);
        if (dy == 0) e = M;
    }
    const unsigned l = g_pl0[t];
    const unsigned conn = nbr & l;
    g_pe1[t] = e | conn;
    g_pl1[t] = l & ~conn;
}

// ---------------------------------------------------------------------------
// Kernel 4: hysteresis iteration 2 + final edges*255 float store.
// ---------------------------------------------------------------------------
__global__ void k_hyst2(float* __restrict__ outE) {
    __shared__ float buf[256 * 33];
    const int t0 = blockIdx.x * 256;
    const int t = t0 + threadIdx.x;
    const int w = t % WPR;
    const int rem = t / WPR;
    const int y = rem % IH;
    const int base = t - w;
    unsigned nbr = 0, e = 0;
#pragma unroll
    for (int dy = -1; dy <= 1; dy++) {
        const int yy = y + dy;
        if (yy < 0 || yy >= IH) continue;
        const int rb = base + dy * WPR;
        unsigned L = (w > 0)       ? g_pe1[rb + w - 1] : 0u;
        unsigned M =                 g_pe1[rb + w];
        unsigned R = (w < WPR - 1) ? g_pe1[rb + w + 1] : 0u;
        nbr |= hor3(L, M, R);
        if (dy == 0) e = M;
    }
    const unsigned l = g_pl1[t];
    const unsigned enew = e | (nbr & l);
#pragma unroll
    for (int j = 0; j < 32; j++)
        buf[threadIdx.x * 33 + j] = ((enew >> j) & 1u) ? 255.0f : 0.0f;
    __syncthreads();
    const int gbase = t0 * 32;
#pragma unroll
    for (int i = 0; i < 32; i++) {
        const int k = i * 256 + threadIdx.x;
        outE[gbase + k] = buf[(k >> 5) * 33 + (k & 31)];
    }
}

extern "C" void kernel_launch(void* const* d_in, const int* in_sizes, int n_in,
                              void* d_out, int out_size) {
    const float* x = (const float*)d_in[0];
    float* out       = (float*)d_out;
    float* out_edges = out;
    float* out_mag   = out + NTOT;
    float* out_ang   = out + 2 * NTOT;

    dim3 blk(32, 8, 1);
    dim3 grd(IW / 32, IH / TH, IB);

    k_fused<<<grd, blk>>>(x, out_mag, out_ang);
    k_border<<<(IB * BORDER_WORDS_PER_IMG) / 8, blk>>>(out_mag);
    k_hyst1<<<NWORDS / 256, 256>>>();
    k_hyst2<<<NWORDS / 256, 256>>>(out_edges);
}